// round 8
// baseline (speedup 1.0000x reference)
#include <cuda_runtime.h>
#include <cstdint>

#define NS 2
#define NB 8
#define NC 32
#define NH 128
#define NW 128
#define NM 32
#define RH 64
#define RW 64

#define TILE_FLOATS (RH * RW)          // 4096
#define TILE_BYTES  (TILE_FLOATS * 4)  // 16 KB
#define TILES_PER_BLK 4
#define NUM_TILES (NS * NB * NM * NC)  // 16384

// Each block processes 4 tiles with 2 SMEM buffers:
//   gather tile t into buf[t&1]  (loads: L2 hits via L1)
//   bulk-async store buf -> gmem (TMA engine, full-line writes, off the STG path)
//   overlap: while tile t's store drains, gather tile t+1.
// wait_group.read 1 before reusing a buffer; wait_group.read 0 before exit.

__global__ __launch_bounds__(256) void roi_patch_kernel(
    const float* __restrict__ fm,
    const int*   __restrict__ boxes,
    float*       __restrict__ out)
{
    __shared__ __align__(128) float tile[2][TILE_FLOATS];

    const int lane16 = threadIdx.x & 15;
    const int r0     = threadIdx.x >> 4;     // 0..15
    const int c0     = lane16 << 2;

    uint32_t sbase[2];
    {
        uint64_t t0, t1;
        asm("cvta.to.shared.u64 %0, %1;" : "=l"(t0) : "l"(&tile[0][0]));
        asm("cvta.to.shared.u64 %0, %1;" : "=l"(t1) : "l"(&tile[1][0]));
        sbase[0] = (uint32_t)t0;
        sbase[1] = (uint32_t)t1;
    }

    #pragma unroll
    for (int t = 0; t < TILES_PER_BLK; ++t) {
        const int blk = blockIdx.x * TILES_PER_BLK + t;
        const int buf = t & 1;

        // Make sure the bulk store that last read this buffer has finished
        // reading it (allow 1 outstanding group = the store of tile t-1).
        if (t >= 2 && threadIdx.x == 0) {
            asm volatile("cp.async.bulk.wait_group.read 1;" ::: "memory");
        }
        __syncthreads();

        const int c   = blk & 31;
        const int bm  = (blk >> 5) & 255;
        const int n   = blk >> 13;
        const int b   = bm >> 5;
        const int m   = bm & 31;

        const int4 box = __ldg(reinterpret_cast<const int4*>(boxes)
                               + (n * NB + b) * NM + m);
        const int x1   = box.x;
        const int y1   = box.y;
        const int wbox = box.z - x1;
        const int hbox = box.w - y1;

        const bool p0 = (c0 + 0) < wbox;
        const bool p1 = (c0 + 1) < wbox;
        const bool p2 = (c0 + 2) < wbox;
        const bool p3 = (c0 + 3) < wbox;

        const float* s0 = fm
            + (((size_t)(n * NB + b) * NC + c) * NH + (y1 + r0)) * NW
            + x1 + c0;

        const float2 z2 = make_float2(0.f, 0.f);
        float2 lo[4], hi[4];

        if ((x1 & 1) == 0) {
            #pragma unroll
            for (int i = 0; i < 4; ++i) {
                const bool rv = (r0 + (i << 4)) < hbox;
                const float* s = s0 + (i << 4) * NW;
                lo[i] = (rv && p0) ? __ldg(reinterpret_cast<const float2*>(s))     : z2;
                hi[i] = (rv && p2) ? __ldg(reinterpret_cast<const float2*>(s + 2)) : z2;
            }
        } else {
            #pragma unroll
            for (int i = 0; i < 4; ++i) {
                const bool rv = (r0 + (i << 4)) < hbox;
                const float* s = s0 + (i << 4) * NW;
                float x    = (rv && p0) ? __ldg(s) : 0.f;
                float2 mid = (rv && p1) ? __ldg(reinterpret_cast<const float2*>(s + 1)) : z2;
                float w    = (rv && p3) ? __ldg(s + 3) : 0.f;
                lo[i] = make_float2(x, mid.x);
                hi[i] = make_float2(mid.y, w);
            }
        }

        #pragma unroll
        for (int i = 0; i < 4; ++i) {
            float4 v;
            v.x = lo[i].x;
            v.y = p1 ? lo[i].y : 0.f;
            v.z = p2 ? hi[i].x : 0.f;
            v.w = p3 ? hi[i].y : 0.f;
            *reinterpret_cast<float4*>(&tile[buf][((r0 + (i << 4)) << 6) + c0]) = v;
        }

        __syncthreads();

        if (threadIdx.x == 0) {
            asm volatile("fence.proxy.async.shared::cta;" ::: "memory");
            float* gdst = out + ((size_t)blk << 12);
            asm volatile(
                "cp.async.bulk.global.shared::cta.bulk_group [%0], [%1], %2;"
                :: "l"(gdst), "r"(sbase[buf]), "n"(TILE_BYTES) : "memory");
            asm volatile("cp.async.bulk.commit_group;" ::: "memory");
        }
    }

    // Drain all outstanding bulk stores before SMEM is deallocated.
    if (threadIdx.x == 0) {
        asm volatile("cp.async.bulk.wait_group.read 0;" ::: "memory");
    }
    __syncthreads();
}

extern "C" void kernel_launch(void* const* d_in, const int* in_sizes, int n_in,
                              void* d_out, int out_size)
{
    const float* fm    = (const float*)d_in[0];
    const int*   boxes = (const int*)d_in[1];
    float*       out   = (float*)d_out;

    const int blocks = NUM_TILES / TILES_PER_BLK;   // 4096
    roi_patch_kernel<<<blocks, 256>>>(fm, boxes, out);
}